// round 15
// baseline (speedup 1.0000x reference)
#include <cuda_runtime.h>

// Problem constants
#define Mdim 32
#define Ndim 4
#define Ldim 2048
#define Hdim 64
#define Kdim 5
#define Gg   10
#define Pdim (Ldim - 2 * Gg)   // 2028: periodic interior ring
#define NSTEPS 20

// Fused kernel tiling: 18 tiles * 32 m = 576 CTAs; 4 CTAs/SM -> one wave (<=592)
#define LT 116
#define NT 256
#define NTILES 18              // 18*116 = 2088 >= 2028 (last tile width 56)

// Fused smem layout (floats). Slot j of Z/KB <-> torus x = base - 12 + j.
#define ZS (LT + 24)            // 140: input/k buffer stride (covers [-12, LT+12))
#define HS 148                  // h1 stride (148%32=20 -> spread banks)
#define AW (LT + 20)            // 136: phase A width (h1 slots), /4 = 34
#define BW (LT + 16)            // 132: phase B width (conv-out slots), /4 = 33
#define W2S 520                 // W2 co-stride
#define F_W1 0                  // 1280
#define F_B1 1280               // 64
#define F_W2 1344               // 2080 (k padded to 8, pads unread)
#define F_B2 3424               // 4
#define F_Z  3428               // 4*140 = 560
#define F_KB (F_Z + Ndim * ZS)  // 3988
#define F_H  (F_KB + Ndim * ZS) // 4548
#define F_TOT (F_H + Hdim * HS) // 14020 floats = 56080 B -> 4 CTAs/SM

// Stage-1 (raw) kernel: own tiling (index math assumes 256-wide tiles)
#define LT1 256
#define NTILES1 8
#define S_SU_STR 264
#define S_SH_STR 264
#define S_W1 0
#define S_B1 (S_W1 + Hdim * Ndim * Kdim)
#define S_W2 (S_B1 + Hdim)
#define S_B2 (S_W2 + Ndim * Hdim * Kdim)
#define S_SU (S_B2 + Ndim)
#define S_SH (S_SU + Ndim * S_SU_STR)
#define S_TOT (S_SH + Hdim * S_SH_STR)   // 20580 floats

// Torus-state scratch (no cudaMalloc allowed)
__device__ float g_k1[Mdim * Ndim * Pdim];
__device__ float g_s0[Mdim * Ndim * Pdim];
__device__ float g_s1[Mdim * Ndim * Pdim];

__device__ __forceinline__ float my_tanh(float x) {
    float e = __expf(2.0f * x);
    return 1.0f - __fdividef(2.0f, e + 1.0f);
}

// ===================== Stage-1 kernel (raw domain, step 1 only) ==============
// k1 = bdry(z0 + h f(z0)) with raw zero-pad conv; writes TORUS layout.
__global__ void __launch_bounds__(NT)
stage1_raw_kernel(const float* __restrict__ z,
                  float* __restrict__ k1t,
                  const float* __restrict__ W1, const float* __restrict__ b1,
                  const float* __restrict__ W2, const float* __restrict__ b2,
                  float h)
{
    extern __shared__ float s[];
    const int tid  = threadIdx.x;
    const int m    = blockIdx.y;
    const int base = blockIdx.x * LT1;

    for (int i = tid; i < Hdim * Ndim * Kdim; i += NT) s[S_W1 + i] = W1[i];
    for (int i = tid; i < Hdim; i += NT)               s[S_B1 + i] = b1[i];
    for (int i = tid; i < Ndim * Hdim * Kdim; i += NT) s[S_W2 + i] = W2[i];
    for (int i = tid; i < Ndim; i += NT)               s[S_B2 + i] = b2[i];

    for (int t = tid; t < Ndim * S_SU_STR; t += NT) {
        int ci = t / S_SU_STR;
        int j  = t - ci * S_SU_STR;
        int gx = base - 4 + j;
        float v = 0.0f;
        if (gx >= 0 && gx < Ldim) v = z[(m * Ndim + ci) * Ldim + gx];
        s[S_SU + ci * S_SU_STR + j] = v;
    }
    __syncthreads();

    {   // Phase A
        const int co   = tid >> 2;
        const int psub = tid & 3;
        float w1r[Ndim][Kdim];
#pragma unroll
        for (int ci = 0; ci < Ndim; ci++)
#pragma unroll
            for (int k = 0; k < Kdim; k++)
                w1r[ci][k] = s[S_W1 + (co * Ndim + ci) * Kdim + k];
        const float b1c = s[S_B1 + co];

        for (int pb = psub; pb < (LT1 + 4) / 4; pb += 4) {
            const int pp0 = pb * 4;
            float acc[4] = {b1c, b1c, b1c, b1c};
#pragma unroll
            for (int ci = 0; ci < Ndim; ci++) {
                const float* sup = &s[S_SU + ci * S_SU_STR + pp0];
                float4 va = *(const float4*)(sup);
                float4 vb = *(const float4*)(sup + 4);
                float x[8] = {va.x, va.y, va.z, va.w, vb.x, vb.y, vb.z, vb.w};
#pragma unroll
                for (int j = 0; j < 4; j++)
#pragma unroll
                    for (int k = 0; k < Kdim; k++)
                        acc[j] = fmaf(w1r[ci][k], x[j + k], acc[j]);
            }
#pragma unroll
            for (int j = 0; j < 4; j++) {
                int hx = base - 2 + pp0 + j;
                float v = (hx >= 0 && hx < Ldim) ? my_tanh(acc[j]) : 0.0f;
                s[S_SH + co * S_SH_STR + pp0 + j] = v;
            }
        }
    }
    __syncthreads();

    {   // Phase B: k1 = z + h * conv2(h1); torus write
        const int co = tid & 3;
        const int p0 = (tid >> 2) * 4;

        const float b2c = s[S_B2 + co];
        float acc[4] = {b2c, b2c, b2c, b2c};

#pragma unroll 8
        for (int ci = 0; ci < Hdim; ci++) {
            const float* shp = &s[S_SH + ci * S_SH_STR + p0];
            float4 va = *(const float4*)(shp);
            float4 vb = *(const float4*)(shp + 4);
            float x[8] = {va.x, va.y, va.z, va.w, vb.x, vb.y, vb.z, vb.w};
            const float* wp = &s[S_W2 + (co * Hdim + ci) * Kdim];
            float wk[Kdim];
#pragma unroll
            for (int k = 0; k < Kdim; k++) wk[k] = wp[k];
#pragma unroll
            for (int j = 0; j < 4; j++)
#pragma unroll
                for (int k = 0; k < Kdim; k++)
                    acc[j] = fmaf(wk[k], x[j + k], acc[j]);
        }

        const int row = (m * Ndim + co) * Ldim;
        float4 zv = *(const float4*)&z[row + base + p0];
        float zz[4] = {zv.x, zv.y, zv.z, zv.w};
        const int rowT = (m * Ndim + co) * Pdim;

#pragma unroll
        for (int j = 0; j < 4; j++) {
            float val = zz[j] + h * acc[j];
            int x = base + p0 + j;
            if (x >= Gg && x < Ldim - Gg) k1t[rowT + (x - Gg)] = val;
        }
    }
}

// ===================== Fused per-step kernel (torus domain) ==================
// Runs RK stages (skip1 ? {2,3} : {1,2,3}) for one time step on the ring.
__global__ void __launch_bounds__(NT, 4)
fused_step_kernel(const float* __restrict__ zin,   // torus state (or raw z0 if firstRaw)
                  const float* __restrict__ k1in,  // torus k1 (used iff skip1)
                  float* __restrict__ zout,        // torus next state (iff !lastOut)
                  float* __restrict__ outF,        // raw final output (iff lastOut)
                  const float* __restrict__ W1, const float* __restrict__ b1,
                  const float* __restrict__ W2, const float* __restrict__ b2,
                  int firstRaw, int skip1, int lastOut)
{
    extern __shared__ float s[];
    const int tid  = threadIdx.x;
    const int m    = blockIdx.y;
    const int base = blockIdx.x * LT;
    const float h  = 1.0f / (float)NSTEPS;

    // ---- weights ----
    for (int i = tid; i < Hdim * Ndim * Kdim; i += NT) s[F_W1 + i] = W1[i];
    for (int i = tid; i < Hdim; i += NT)               s[F_B1 + i] = b1[i];
    for (int i = tid; i < Ndim * Hdim * Kdim; i += NT) {
        int co = i / (Hdim * Kdim);
        int r  = i - co * (Hdim * Kdim);
        int ci = r / Kdim, k = r - ci * Kdim;
        s[F_W2 + co * W2S + ci * 8 + k] = W2[i];       // pads k=5..7 never read
    }
    for (int i = tid; i < Ndim; i += NT)               s[F_B2 + i] = b2[i];

    // ---- z tile (torus wrap; firstRaw reads raw z0 interior at Gg+t) ----
    {
        const int zpitch = firstRaw ? Ldim : Pdim;
        const int zoff   = firstRaw ? Gg : 0;
        for (int j = tid; j < Ndim * ZS; j += NT) {
            int ci = j / ZS;
            int jj = j - ci * ZS;
            int t  = base - 12 + jj;
            if (t < 0) t += Pdim; else if (t >= Pdim) t -= Pdim;
            s[F_Z + ci * ZS + jj] = zin[(m * Ndim + ci) * zpitch + zoff + t];
        }
    }
    // ---- k1 tile from gmem when skipping stage 1 ----
    if (skip1) {
        for (int j = tid; j < Ndim * ZS; j += NT) {
            int ci = j / ZS;
            int jj = j - ci * ZS;
            int t  = base - 12 + jj;
            if (t < 0) t += Pdim; else if (t >= Pdim) t -= Pdim;
            s[F_KB + ci * ZS + jj] = k1in[(m * Ndim + ci) * Pdim + t];
        }
    }
    __syncthreads();

    // per-thread conv1 weights (co_a fixed across stages)
    const int co_a = tid >> 2;
    const int psub = tid & 3;
    float w1r[Ndim][Kdim];
#pragma unroll
    for (int ci = 0; ci < Ndim; ci++)
#pragma unroll
        for (int k = 0; k < Kdim; k++)
            w1r[ci][k] = s[F_W1 + (co_a * Ndim + ci) * Kdim + k];
    const float b1c = s[F_B1 + co_a];
    const float b2c = s[F_B2 + (tid & 3)];

    const float AL[3] = {1.0f, 0.75f, 1.0f / 3.0f};
    const float BE[3] = {0.0f, 0.25f, 2.0f / 3.0f};
    const float GA[3] = {h, 0.25f * h, (2.0f / 3.0f) * h};

    for (int st = skip1 ? 1 : 0; st < 3; st++) {
        const float* uin = &s[(st == 0) ? F_Z : F_KB];

        // ---- Phase A: h1[hj] = tanh(conv1(uin)), hj in [0, AW) ----
        for (int hq = psub; hq < AW / 4; hq += 4) {
            const int jh0 = hq * 4;
            float acc[4] = {b1c, b1c, b1c, b1c};
#pragma unroll
            for (int ci = 0; ci < Ndim; ci++) {
                const float* up = uin + ci * ZS + jh0;
                float4 va = *(const float4*)(up);
                float4 vb = *(const float4*)(up + 4);
                float x[8] = {va.x, va.y, va.z, va.w, vb.x, vb.y, vb.z, vb.w};
#pragma unroll
                for (int j = 0; j < 4; j++)
#pragma unroll
                    for (int k = 0; k < Kdim; k++)
                        acc[j] = fmaf(w1r[ci][k], x[j + k], acc[j]);
            }
            float4 hv;
            hv.x = my_tanh(acc[0]);
            hv.y = my_tanh(acc[1]);
            hv.z = my_tanh(acc[2]);
            hv.w = my_tanh(acc[3]);
            *(float4*)&s[F_H + co_a * HS + jh0] = hv;
        }
        __syncthreads();

        // ---- Phase B: out[oj] = AL*z + BE*uin + GA*(conv2(h1)+b2) ----
        {
            const int co = tid & 3;
            const float al = AL[st], be = BE[st], ga = GA[st];
            const float* wb   = &s[F_W2 + co * W2S];
            const float* zrow = &s[F_Z + co * ZS];
            const float* urow = uin + co * ZS;
            float* krow = &s[F_KB + co * ZS];

            for (int q = tid >> 2; q < BW / 4; q += 64) {
                const int oj = q * 4;
                float a0 = 0.f, a1 = 0.f, a2 = 0.f, a3 = 0.f;
                const float* hb = &s[F_H + oj];
#pragma unroll 4
                for (int ci = 0; ci < Hdim; ci++) {
                    const float* hp = hb + ci * HS;
                    float4 va = *(const float4*)(hp);
                    float4 vb = *(const float4*)(hp + 4);
                    const float* wp = wb + ci * 8;
                    float4 w4 = *(const float4*)(wp);
                    float  wk = wp[4];

                    a0 = fmaf(w4.x, va.x, a0);
                    a1 = fmaf(w4.x, va.y, a1);
                    a2 = fmaf(w4.x, va.z, a2);
                    a3 = fmaf(w4.x, va.w, a3);
                    a0 = fmaf(w4.y, va.y, a0);
                    a1 = fmaf(w4.y, va.z, a1);
                    a2 = fmaf(w4.y, va.w, a2);
                    a3 = fmaf(w4.y, vb.x, a3);
                    a0 = fmaf(w4.z, va.z, a0);
                    a1 = fmaf(w4.z, va.w, a1);
                    a2 = fmaf(w4.z, vb.x, a2);
                    a3 = fmaf(w4.z, vb.y, a3);
                    a0 = fmaf(w4.w, va.w, a0);
                    a1 = fmaf(w4.w, vb.x, a1);
                    a2 = fmaf(w4.w, vb.y, a2);
                    a3 = fmaf(w4.w, vb.z, a3);
                    a0 = fmaf(wk, vb.x, a0);
                    a1 = fmaf(wk, vb.y, a1);
                    a2 = fmaf(wk, vb.z, a2);
                    a3 = fmaf(wk, vb.w, a3);
                }
                float4 zq = *(const float4*)(zrow + oj + 4);
                float4 uq = *(const float4*)(urow + oj + 4);
                float4 kv;
                kv.x = al * zq.x + be * uq.x + ga * (a0 + b2c);
                kv.y = al * zq.y + be * uq.y + ga * (a1 + b2c);
                kv.z = al * zq.z + be * uq.z + ga * (a2 + b2c);
                kv.w = al * zq.w + be * uq.w + ga * (a3 + b2c);
                *(float4*)(krow + oj + 4) = kv;      // in-place k update (safe)
            }
        }
        __syncthreads();
    }

    // ---- epilogue: KB slot (p+12) holds z_new at torus t = base + p ----
    const int Wt = (Pdim - base < LT) ? (Pdim - base) : LT;
    if (!lastOut) {
#pragma unroll
        for (int ci = 0; ci < Ndim; ci++) {
            float* zo = &zout[(m * Ndim + ci) * Pdim + base];
            const float* kb = &s[F_KB + ci * ZS + 12];
            for (int p = tid; p < Wt; p += NT) zo[p] = kb[p];
        }
    } else {
#pragma unroll
        for (int ci = 0; ci < Ndim; ci++) {
            const int row = (m * Ndim + ci) * Ldim;
            const float* kb = &s[F_KB + ci * ZS + 12];
            for (int p = tid; p < Wt; p += NT) {
                float v = kb[p];
                int t = base + p;
                outF[row + Gg + t] = v;                              // interior
                if (t < Gg)         outF[row + Ldim - Gg + t] = v;   // upper ghosts
                if (t >= Pdim - Gg) outF[row + t - (Pdim - Gg)] = v; // lower ghosts
            }
        }
    }
}

extern "C" void kernel_launch(void* const* d_in, const int* in_sizes, int n_in,
                              void* d_out, int out_size) {
    const float* z0 = (const float*)d_in[0];
    const float* W1 = (const float*)d_in[1];
    const float* b1 = (const float*)d_in[2];
    const float* W2 = (const float*)d_in[3];
    const float* b2 = (const float*)d_in[4];
    float* out = (float*)d_out;

    float *K1, *S0, *S1;
    cudaGetSymbolAddress((void**)&K1, g_k1);
    cudaGetSymbolAddress((void**)&S0, g_s0);
    cudaGetSymbolAddress((void**)&S1, g_s1);

    const size_t smem1 = S_TOT * sizeof(float);
    const size_t smemF = F_TOT * sizeof(float);
    cudaFuncSetAttribute(stage1_raw_kernel,
                         cudaFuncAttributeMaxDynamicSharedMemorySize, (int)smem1);
    cudaFuncSetAttribute(fused_step_kernel,
                         cudaFuncAttributeMaxDynamicSharedMemorySize, (int)smemF);

    dim3 grid1(NTILES1, Mdim);
    dim3 gridF(NTILES, Mdim);
    dim3 blk(NT);
    const float h = 1.0f / (float)NSTEPS;

    // Step 1, stage 1: raw domain (z0 ghosts are NOT periodic) -> torus k1
    stage1_raw_kernel<<<grid1, blk, smem1>>>(z0, K1, W1, b1, W2, b2, h);
    // Step 1, stages 2-3: fused, z read raw-interior, k1 from gmem
    fused_step_kernel<<<gridF, blk, smemF>>>(z0, K1, S0, out, W1, b1, W2, b2,
                                             /*firstRaw=*/1, /*skip1=*/1, /*last=*/0);
    // Steps 2..NSTEPS: fully fused on the torus
    float* cur = S0;
    float* nxt = S1;
    for (int st = 1; st < NSTEPS; st++) {
        int last = (st == NSTEPS - 1);
        fused_step_kernel<<<gridF, blk, smemF>>>(cur, K1, nxt, out, W1, b1, W2, b2,
                                                 0, 0, last);
        float* tmp = cur; cur = nxt; nxt = tmp;
    }
}

// round 16
// speedup vs baseline: 1.0798x; 1.0798x over previous
#include <cuda_runtime.h>

// Problem constants
#define Mdim 32
#define Ndim 4
#define Ldim 2048
#define Hdim 64
#define Kdim 5
#define Gg   10
#define Pdim (Ldim - 2 * Gg)   // 2028: periodic interior ring
#define NSTEPS 20

// Fused kernel tiling: 9 tiles * 32 m = 288 CTAs -> 140/148 SMs hold 2 CTAs
#define LT 228
#define NT 256
#define NTILES 9               // 9*228 = 2052 >= 2028 (last tile width 204)

// Fused smem layout (floats). Slot j of Z/KB <-> torus x = base - 12 + j.
#define ZS 260                  // input/k row stride (covers [-12, 248); mod32=4 spread)
#define HS 260                  // h1 stride
#define AW (LT + 20)            // 248: phase A width (h1 slots), /4 = 62
#define NQP 31                  // phase B: 31 active groups x 2 quads = 62 quads
#define W2S 520                 // W2 co-stride
#define F_W1 0                  // 1280
#define F_B1 1280               // 64
#define F_W2 1344               // 2080 (k padded to 8, pads unread)
#define F_B2 3424               // 4
#define F_Z  3428               // 4*260 = 1040
#define F_KB (F_Z + Ndim * ZS)  // 4468
#define F_H  (F_KB + Ndim * ZS) // 5508
#define F_TOT (F_H + Hdim * HS) // 22148 floats = 88592 B -> 2 CTAs/SM

// Stage-1 (raw) kernel: own tiling (index math assumes 256-wide tiles)
#define LT1 256
#define NTILES1 8
#define S_SU_STR 264
#define S_SH_STR 264
#define S_W1 0
#define S_B1 (S_W1 + Hdim * Ndim * Kdim)
#define S_W2 (S_B1 + Hdim)
#define S_B2 (S_W2 + Ndim * Hdim * Kdim)
#define S_SU (S_B2 + Ndim)
#define S_SH (S_SU + Ndim * S_SU_STR)
#define S_TOT (S_SH + Hdim * S_SH_STR)   // 20580 floats

// Torus-state scratch (no cudaMalloc allowed)
__device__ float g_k1[Mdim * Ndim * Pdim];
__device__ float g_s0[Mdim * Ndim * Pdim];
__device__ float g_s1[Mdim * Ndim * Pdim];

__device__ __forceinline__ float my_tanh(float x) {
    float e = __expf(2.0f * x);
    return 1.0f - __fdividef(2.0f, e + 1.0f);
}

// ===================== Stage-1 kernel (raw domain, step 1 only) ==============
// k1 = bdry(z0 + h f(z0)) with raw zero-pad conv; writes TORUS layout.
__global__ void __launch_bounds__(NT)
stage1_raw_kernel(const float* __restrict__ z,
                  float* __restrict__ k1t,
                  const float* __restrict__ W1, const float* __restrict__ b1,
                  const float* __restrict__ W2, const float* __restrict__ b2,
                  float h)
{
    extern __shared__ float s[];
    const int tid  = threadIdx.x;
    const int m    = blockIdx.y;
    const int base = blockIdx.x * LT1;

    for (int i = tid; i < Hdim * Ndim * Kdim; i += NT) s[S_W1 + i] = W1[i];
    for (int i = tid; i < Hdim; i += NT)               s[S_B1 + i] = b1[i];
    for (int i = tid; i < Ndim * Hdim * Kdim; i += NT) s[S_W2 + i] = W2[i];
    for (int i = tid; i < Ndim; i += NT)               s[S_B2 + i] = b2[i];

    for (int t = tid; t < Ndim * S_SU_STR; t += NT) {
        int ci = t / S_SU_STR;
        int j  = t - ci * S_SU_STR;
        int gx = base - 4 + j;
        float v = 0.0f;
        if (gx >= 0 && gx < Ldim) v = z[(m * Ndim + ci) * Ldim + gx];
        s[S_SU + ci * S_SU_STR + j] = v;
    }
    __syncthreads();

    {   // Phase A
        const int co   = tid >> 2;
        const int psub = tid & 3;
        float w1r[Ndim][Kdim];
#pragma unroll
        for (int ci = 0; ci < Ndim; ci++)
#pragma unroll
            for (int k = 0; k < Kdim; k++)
                w1r[ci][k] = s[S_W1 + (co * Ndim + ci) * Kdim + k];
        const float b1c = s[S_B1 + co];

        for (int pb = psub; pb < (LT1 + 4) / 4; pb += 4) {
            const int pp0 = pb * 4;
            float acc[4] = {b1c, b1c, b1c, b1c};
#pragma unroll
            for (int ci = 0; ci < Ndim; ci++) {
                const float* sup = &s[S_SU + ci * S_SU_STR + pp0];
                float4 va = *(const float4*)(sup);
                float4 vb = *(const float4*)(sup + 4);
                float x[8] = {va.x, va.y, va.z, va.w, vb.x, vb.y, vb.z, vb.w};
#pragma unroll
                for (int j = 0; j < 4; j++)
#pragma unroll
                    for (int k = 0; k < Kdim; k++)
                        acc[j] = fmaf(w1r[ci][k], x[j + k], acc[j]);
            }
#pragma unroll
            for (int j = 0; j < 4; j++) {
                int hx = base - 2 + pp0 + j;
                float v = (hx >= 0 && hx < Ldim) ? my_tanh(acc[j]) : 0.0f;
                s[S_SH + co * S_SH_STR + pp0 + j] = v;
            }
        }
    }
    __syncthreads();

    {   // Phase B: k1 = z + h * conv2(h1); torus write
        const int co = tid & 3;
        const int p0 = (tid >> 2) * 4;

        const float b2c = s[S_B2 + co];
        float acc[4] = {b2c, b2c, b2c, b2c};

#pragma unroll 8
        for (int ci = 0; ci < Hdim; ci++) {
            const float* shp = &s[S_SH + ci * S_SH_STR + p0];
            float4 va = *(const float4*)(shp);
            float4 vb = *(const float4*)(shp + 4);
            float x[8] = {va.x, va.y, va.z, va.w, vb.x, vb.y, vb.z, vb.w};
            const float* wp = &s[S_W2 + (co * Hdim + ci) * Kdim];
            float wk[Kdim];
#pragma unroll
            for (int k = 0; k < Kdim; k++) wk[k] = wp[k];
#pragma unroll
            for (int j = 0; j < 4; j++)
#pragma unroll
                for (int k = 0; k < Kdim; k++)
                    acc[j] = fmaf(wk[k], x[j + k], acc[j]);
        }

        const int row = (m * Ndim + co) * Ldim;
        float4 zv = *(const float4*)&z[row + base + p0];
        float zz[4] = {zv.x, zv.y, zv.z, zv.w};
        const int rowT = (m * Ndim + co) * Pdim;

#pragma unroll
        for (int j = 0; j < 4; j++) {
            float val = zz[j] + h * acc[j];
            int x = base + p0 + j;
            if (x >= Gg && x < Ldim - Gg) k1t[rowT + (x - Gg)] = val;
        }
    }
}

// ===================== Fused per-step kernel (torus domain) ==================
// Runs RK stages (skip1 ? {2,3} : {1,2,3}) for one time step on the ring.
__global__ void __launch_bounds__(NT)
fused_step_kernel(const float* __restrict__ zin,   // torus state (or raw z0 if firstRaw)
                  const float* __restrict__ k1in,  // torus k1 (used iff skip1)
                  float* __restrict__ zout,        // torus next state (iff !lastOut)
                  float* __restrict__ outF,        // raw final output (iff lastOut)
                  const float* __restrict__ W1, const float* __restrict__ b1,
                  const float* __restrict__ W2, const float* __restrict__ b2,
                  int firstRaw, int skip1, int lastOut)
{
    extern __shared__ float s[];
    const int tid  = threadIdx.x;
    const int m    = blockIdx.y;
    const int base = blockIdx.x * LT;
    const float h  = 1.0f / (float)NSTEPS;

    // ---- weights ----
    for (int i = tid; i < Hdim * Ndim * Kdim; i += NT) s[F_W1 + i] = W1[i];
    for (int i = tid; i < Hdim; i += NT)               s[F_B1 + i] = b1[i];
    for (int i = tid; i < Ndim * Hdim * Kdim; i += NT) {
        int co = i / (Hdim * Kdim);
        int r  = i - co * (Hdim * Kdim);
        int ci = r / Kdim, k = r - ci * Kdim;
        s[F_W2 + co * W2S + ci * 8 + k] = W2[i];       // pads k=5..7 never read
    }
    for (int i = tid; i < Ndim; i += NT)               s[F_B2 + i] = b2[i];

    // ---- z tile (torus wrap; firstRaw reads raw z0 interior at Gg+t) ----
    {
        const int zpitch = firstRaw ? Ldim : Pdim;
        const int zoff   = firstRaw ? Gg : 0;
        for (int j = tid; j < Ndim * ZS; j += NT) {
            int ci = j / ZS;
            int jj = j - ci * ZS;
            int t  = base - 12 + jj;
            if (t < 0) t += Pdim; else if (t >= Pdim) t -= Pdim;
            s[F_Z + ci * ZS + jj] = zin[(m * Ndim + ci) * zpitch + zoff + t];
        }
    }
    // ---- k1 tile from gmem when skipping stage 1 ----
    if (skip1) {
        for (int j = tid; j < Ndim * ZS; j += NT) {
            int ci = j / ZS;
            int jj = j - ci * ZS;
            int t  = base - 12 + jj;
            if (t < 0) t += Pdim; else if (t >= Pdim) t -= Pdim;
            s[F_KB + ci * ZS + jj] = k1in[(m * Ndim + ci) * Pdim + t];
        }
    }
    __syncthreads();

    // per-thread conv1 weights (co_a fixed across stages)
    const int co_a = tid >> 2;
    const int psub = tid & 3;
    float w1r[Ndim][Kdim];
#pragma unroll
    for (int ci = 0; ci < Ndim; ci++)
#pragma unroll
        for (int k = 0; k < Kdim; k++)
            w1r[ci][k] = s[F_W1 + (co_a * Ndim + ci) * Kdim + k];
    const float b1c = s[F_B1 + co_a];
    const float b2c = s[F_B2 + (tid & 3)];

    const float AL[3] = {1.0f, 0.75f, 1.0f / 3.0f};
    const float BE[3] = {0.0f, 0.25f, 2.0f / 3.0f};
    const float GA[3] = {h, 0.25f * h, (2.0f / 3.0f) * h};

    for (int st = skip1 ? 1 : 0; st < 3; st++) {
        const float* uin = &s[(st == 0) ? F_Z : F_KB];

        // ---- Phase A: h1[hj] = tanh(conv1(uin)), hj in [0, AW) ----
        for (int hq = psub; hq < AW / 4; hq += 4) {
            const int jh0 = hq * 4;
            float acc[4] = {b1c, b1c, b1c, b1c};
#pragma unroll
            for (int ci = 0; ci < Ndim; ci++) {
                const float* up = uin + ci * ZS + jh0;
                float4 va = *(const float4*)(up);
                float4 vb = *(const float4*)(up + 4);
                float x[8] = {va.x, va.y, va.z, va.w, vb.x, vb.y, vb.z, vb.w};
#pragma unroll
                for (int j = 0; j < 4; j++)
#pragma unroll
                    for (int k = 0; k < Kdim; k++)
                        acc[j] = fmaf(w1r[ci][k], x[j + k], acc[j]);
            }
            float4 hv;
            hv.x = my_tanh(acc[0]);
            hv.y = my_tanh(acc[1]);
            hv.z = my_tanh(acc[2]);
            hv.w = my_tanh(acc[3]);
            *(float4*)&s[F_H + co_a * HS + jh0] = hv;
        }
        __syncthreads();

        // ---- Phase B: paired quads (g, g+NQP) share one weight load ----
        // out[slot q=oj+4+j] = AL*z + BE*uin + GA*(conv2(h1)+b2)
        {
            const int co = tid & 3;
            const int g  = tid >> 2;          // 0..63; active g < NQP
            if (g < NQP) {
                const int oj1 = g * 4;        // quads 0..30
                const int oj2 = (g + NQP) * 4;// quads 31..61
                const float al = AL[st], be = BE[st], ga = GA[st];
                const float* wb   = &s[F_W2 + co * W2S];
                const float* zrow = &s[F_Z + co * ZS];
                const float* urow = uin + co * ZS;
                float* krow = &s[F_KB + co * ZS];

                float a0 = 0.f, a1 = 0.f, a2 = 0.f, a3 = 0.f;
                float c0 = 0.f, c1 = 0.f, c2 = 0.f, c3 = 0.f;
                const float* hb1 = &s[F_H + oj1];
                const float* hb2 = &s[F_H + oj2];
#pragma unroll 2
                for (int ci = 0; ci < Hdim; ci++) {
                    const float* hp1 = hb1 + ci * HS;
                    const float* hp2 = hb2 + ci * HS;
                    float4 va = *(const float4*)(hp1);
                    float4 vb = *(const float4*)(hp1 + 4);
                    float4 vc = *(const float4*)(hp2);
                    float4 vd = *(const float4*)(hp2 + 4);
                    const float* wp = wb + ci * 8;
                    float4 w4 = *(const float4*)(wp);
                    float  wk = wp[4];

                    a0 = fmaf(w4.x, va.x, a0);
                    a1 = fmaf(w4.x, va.y, a1);
                    a2 = fmaf(w4.x, va.z, a2);
                    a3 = fmaf(w4.x, va.w, a3);
                    c0 = fmaf(w4.x, vc.x, c0);
                    c1 = fmaf(w4.x, vc.y, c1);
                    c2 = fmaf(w4.x, vc.z, c2);
                    c3 = fmaf(w4.x, vc.w, c3);
                    a0 = fmaf(w4.y, va.y, a0);
                    a1 = fmaf(w4.y, va.z, a1);
                    a2 = fmaf(w4.y, va.w, a2);
                    a3 = fmaf(w4.y, vb.x, a3);
                    c0 = fmaf(w4.y, vc.y, c0);
                    c1 = fmaf(w4.y, vc.z, c1);
                    c2 = fmaf(w4.y, vc.w, c2);
                    c3 = fmaf(w4.y, vd.x, c3);
                    a0 = fmaf(w4.z, va.z, a0);
                    a1 = fmaf(w4.z, va.w, a1);
                    a2 = fmaf(w4.z, vb.x, a2);
                    a3 = fmaf(w4.z, vb.y, a3);
                    c0 = fmaf(w4.z, vc.z, c0);
                    c1 = fmaf(w4.z, vc.w, c1);
                    c2 = fmaf(w4.z, vd.x, c2);
                    c3 = fmaf(w4.z, vd.y, c3);
                    a0 = fmaf(w4.w, va.w, a0);
                    a1 = fmaf(w4.w, vb.x, a1);
                    a2 = fmaf(w4.w, vb.y, a2);
                    a3 = fmaf(w4.w, vb.z, a3);
                    c0 = fmaf(w4.w, vc.w, c0);
                    c1 = fmaf(w4.w, vd.x, c1);
                    c2 = fmaf(w4.w, vd.y, c2);
                    c3 = fmaf(w4.w, vd.z, c3);
                    a0 = fmaf(wk, vb.x, a0);
                    a1 = fmaf(wk, vb.y, a1);
                    a2 = fmaf(wk, vb.z, a2);
                    a3 = fmaf(wk, vb.w, a3);
                    c0 = fmaf(wk, vd.x, c0);
                    c1 = fmaf(wk, vd.y, c1);
                    c2 = fmaf(wk, vd.z, c2);
                    c3 = fmaf(wk, vd.w, c3);
                }
                float4 zq1 = *(const float4*)(zrow + oj1 + 4);
                float4 uq1 = *(const float4*)(urow + oj1 + 4);
                float4 zq2 = *(const float4*)(zrow + oj2 + 4);
                float4 uq2 = *(const float4*)(urow + oj2 + 4);
                float4 kv1, kv2;
                kv1.x = al * zq1.x + be * uq1.x + ga * (a0 + b2c);
                kv1.y = al * zq1.y + be * uq1.y + ga * (a1 + b2c);
                kv1.z = al * zq1.z + be * uq1.z + ga * (a2 + b2c);
                kv1.w = al * zq1.w + be * uq1.w + ga * (a3 + b2c);
                kv2.x = al * zq2.x + be * uq2.x + ga * (c0 + b2c);
                kv2.y = al * zq2.y + be * uq2.y + ga * (c1 + b2c);
                kv2.z = al * zq2.z + be * uq2.z + ga * (c2 + b2c);
                kv2.w = al * zq2.w + be * uq2.w + ga * (c3 + b2c);
                *(float4*)(krow + oj1 + 4) = kv1;   // in-place k update (safe)
                *(float4*)(krow + oj2 + 4) = kv2;
            }
        }
        __syncthreads();
    }

    // ---- epilogue: KB slot (p+12) holds z_new at torus t = base + p ----
    const int Wt = (Pdim - base < LT) ? (Pdim - base) : LT;
    if (!lastOut) {
#pragma unroll
        for (int ci = 0; ci < Ndim; ci++) {
            float* zo = &zout[(m * Ndim + ci) * Pdim + base];
            const float* kb = &s[F_KB + ci * ZS + 12];
            for (int p = tid; p < Wt; p += NT) zo[p] = kb[p];
        }
    } else {
#pragma unroll
        for (int ci = 0; ci < Ndim; ci++) {
            const int row = (m * Ndim + ci) * Ldim;
            const float* kb = &s[F_KB + ci * ZS + 12];
            for (int p = tid; p < Wt; p += NT) {
                float v = kb[p];
                int t = base + p;
                outF[row + Gg + t] = v;                              // interior
                if (t < Gg)         outF[row + Ldim - Gg + t] = v;   // upper ghosts
                if (t >= Pdim - Gg) outF[row + t - (Pdim - Gg)] = v; // lower ghosts
            }
        }
    }
}

extern "C" void kernel_launch(void* const* d_in, const int* in_sizes, int n_in,
                              void* d_out, int out_size) {
    const float* z0 = (const float*)d_in[0];
    const float* W1 = (const float*)d_in[1];
    const float* b1 = (const float*)d_in[2];
    const float* W2 = (const float*)d_in[3];
    const float* b2 = (const float*)d_in[4];
    float* out = (float*)d_out;

    float *K1, *S0, *S1;
    cudaGetSymbolAddress((void**)&K1, g_k1);
    cudaGetSymbolAddress((void**)&S0, g_s0);
    cudaGetSymbolAddress((void**)&S1, g_s1);

    const size_t smem1 = S_TOT * sizeof(float);
    const size_t smemF = F_TOT * sizeof(float);
    cudaFuncSetAttribute(stage1_raw_kernel,
                         cudaFuncAttributeMaxDynamicSharedMemorySize, (int)smem1);
    cudaFuncSetAttribute(fused_step_kernel,
                         cudaFuncAttributeMaxDynamicSharedMemorySize, (int)smemF);

    dim3 grid1(NTILES1, Mdim);
    dim3 gridF(NTILES, Mdim);
    dim3 blk(NT);
    const float h = 1.0f / (float)NSTEPS;

    // Step 1, stage 1: raw domain (z0 ghosts are NOT periodic) -> torus k1
    stage1_raw_kernel<<<grid1, blk, smem1>>>(z0, K1, W1, b1, W2, b2, h);
    // Step 1, stages 2-3: fused, z read raw-interior, k1 from gmem
    fused_step_kernel<<<gridF, blk, smemF>>>(z0, K1, S0, out, W1, b1, W2, b2,
                                             /*firstRaw=*/1, /*skip1=*/1, /*last=*/0);
    // Steps 2..NSTEPS: fully fused on the torus
    float* cur = S0;
    float* nxt = S1;
    for (int st = 1; st < NSTEPS; st++) {
        int last = (st == NSTEPS - 1);
        fused_step_kernel<<<gridF, blk, smemF>>>(cur, K1, nxt, out, W1, b1, W2, b2,
                                                 0, 0, last);
        float* tmp = cur; cur = nxt; nxt = tmp;
    }
}

// round 17
// speedup vs baseline: 1.1954x; 1.1070x over previous
#include <cuda_runtime.h>

// Problem constants
#define Mdim 32
#define Ndim 4
#define Ldim 2048
#define Hdim 64
#define Kdim 5
#define Gg   10
#define Pdim (Ldim - 2 * Gg)   // 2028: periodic interior ring
#define NSTEPS 20

// Fused kernel tiling: 9 tiles * 32 m = 288 CTAs -> 140/148 SMs hold 2 CTAs
#define LT 228
#define NT 256
#define NTILES 9               // 9*228 = 2052 >= 2028 (last tile width 204)

// Fused smem layout (floats). Slot j of Z/KB <-> torus x = base - 12 + j.
#define ZS (LT + 24)            // 252: input/k buffer stride (covers [-12, LT+12))
#define HS 260                  // h1 stride (260%32=4 -> conflict-free A writes)
#define AW (LT + 20)            // 248: phase A width (h1 slots)
#define BW (LT + 16)            // 244: phase B width (conv-out slots)
#define W2S 520                 // W2 co-stride
#define F_W1 0                  // 1280
#define F_B1 1280               // 64
#define F_W2 1344               // 2080 (k padded to 8, pads unread)
#define F_B2 3424               // 4
#define F_Z  3428               // 4*252 = 1008
#define F_KB (F_Z + Ndim * ZS)  // 4436
#define F_H  (F_KB + Ndim * ZS) // 5444
#define F_TOT (F_H + Hdim * HS) // 22084 floats = 88336 B -> 2 CTAs/SM

// Stage-1 (raw) kernel: own tiling (index math assumes 256-wide tiles)
#define LT1 256
#define NTILES1 8
#define S_SU_STR 264
#define S_SH_STR 264
#define S_W1 0
#define S_B1 (S_W1 + Hdim * Ndim * Kdim)
#define S_W2 (S_B1 + Hdim)
#define S_B2 (S_W2 + Ndim * Hdim * Kdim)
#define S_SU (S_B2 + Ndim)
#define S_SH (S_SU + Ndim * S_SU_STR)
#define S_TOT (S_SH + Hdim * S_SH_STR)   // 20580 floats

// Torus-state scratch (no cudaMalloc allowed)
__device__ float g_k1[Mdim * Ndim * Pdim];
__device__ float g_s0[Mdim * Ndim * Pdim];
__device__ float g_s1[Mdim * Ndim * Pdim];

// Native MUFU tanh (sm_75+): 1 op vs 2 MUFU + 4 scalar for the exp-based form.
// abs err ~1.4e-4 -> propagated rel_err ~1e-4 << 1e-3 threshold.
__device__ __forceinline__ float my_tanh(float x) {
    float r;
    asm("tanh.approx.f32 %0, %1;" : "=f"(r) : "f"(x));
    return r;
}

// ===================== Stage-1 kernel (raw domain, step 1 only) ==============
// k1 = bdry(z0 + h f(z0)) with raw zero-pad conv; writes TORUS layout.
__global__ void __launch_bounds__(NT)
stage1_raw_kernel(const float* __restrict__ z,
                  float* __restrict__ k1t,
                  const float* __restrict__ W1, const float* __restrict__ b1,
                  const float* __restrict__ W2, const float* __restrict__ b2,
                  float h)
{
    extern __shared__ float s[];
    const int tid  = threadIdx.x;
    const int m    = blockIdx.y;
    const int base = blockIdx.x * LT1;

    for (int i = tid; i < Hdim * Ndim * Kdim; i += NT) s[S_W1 + i] = W1[i];
    for (int i = tid; i < Hdim; i += NT)               s[S_B1 + i] = b1[i];
    for (int i = tid; i < Ndim * Hdim * Kdim; i += NT) s[S_W2 + i] = W2[i];
    for (int i = tid; i < Ndim; i += NT)               s[S_B2 + i] = b2[i];

    for (int t = tid; t < Ndim * S_SU_STR; t += NT) {
        int ci = t / S_SU_STR;
        int j  = t - ci * S_SU_STR;
        int gx = base - 4 + j;
        float v = 0.0f;
        if (gx >= 0 && gx < Ldim) v = z[(m * Ndim + ci) * Ldim + gx];
        s[S_SU + ci * S_SU_STR + j] = v;
    }
    __syncthreads();

    {   // Phase A
        const int co   = tid >> 2;
        const int psub = tid & 3;
        float w1r[Ndim][Kdim];
#pragma unroll
        for (int ci = 0; ci < Ndim; ci++)
#pragma unroll
            for (int k = 0; k < Kdim; k++)
                w1r[ci][k] = s[S_W1 + (co * Ndim + ci) * Kdim + k];
        const float b1c = s[S_B1 + co];

        for (int pb = psub; pb < (LT1 + 4) / 4; pb += 4) {
            const int pp0 = pb * 4;
            float acc[4] = {b1c, b1c, b1c, b1c};
#pragma unroll
            for (int ci = 0; ci < Ndim; ci++) {
                const float* sup = &s[S_SU + ci * S_SU_STR + pp0];
                float4 va = *(const float4*)(sup);
                float4 vb = *(const float4*)(sup + 4);
                float x[8] = {va.x, va.y, va.z, va.w, vb.x, vb.y, vb.z, vb.w};
#pragma unroll
                for (int j = 0; j < 4; j++)
#pragma unroll
                    for (int k = 0; k < Kdim; k++)
                        acc[j] = fmaf(w1r[ci][k], x[j + k], acc[j]);
            }
#pragma unroll
            for (int j = 0; j < 4; j++) {
                int hx = base - 2 + pp0 + j;
                float v = (hx >= 0 && hx < Ldim) ? my_tanh(acc[j]) : 0.0f;
                s[S_SH + co * S_SH_STR + pp0 + j] = v;
            }
        }
    }
    __syncthreads();

    {   // Phase B: k1 = z + h * conv2(h1); torus write
        const int co = tid & 3;
        const int p0 = (tid >> 2) * 4;

        const float b2c = s[S_B2 + co];
        float acc[4] = {b2c, b2c, b2c, b2c};

#pragma unroll 8
        for (int ci = 0; ci < Hdim; ci++) {
            const float* shp = &s[S_SH + ci * S_SH_STR + p0];
            float4 va = *(const float4*)(shp);
            float4 vb = *(const float4*)(shp + 4);
            float x[8] = {va.x, va.y, va.z, va.w, vb.x, vb.y, vb.z, vb.w};
            const float* wp = &s[S_W2 + (co * Hdim + ci) * Kdim];
            float wk[Kdim];
#pragma unroll
            for (int k = 0; k < Kdim; k++) wk[k] = wp[k];
#pragma unroll
            for (int j = 0; j < 4; j++)
#pragma unroll
                for (int k = 0; k < Kdim; k++)
                    acc[j] = fmaf(wk[k], x[j + k], acc[j]);
        }

        const int row = (m * Ndim + co) * Ldim;
        float4 zv = *(const float4*)&z[row + base + p0];
        float zz[4] = {zv.x, zv.y, zv.z, zv.w};
        const int rowT = (m * Ndim + co) * Pdim;

#pragma unroll
        for (int j = 0; j < 4; j++) {
            float val = zz[j] + h * acc[j];
            int x = base + p0 + j;
            if (x >= Gg && x < Ldim - Gg) k1t[rowT + (x - Gg)] = val;
        }
    }
}

// ===================== Fused per-step kernel (torus domain) ==================
// Runs RK stages (skip1 ? {2,3} : {1,2,3}) for one time step on the ring.
__global__ void __launch_bounds__(NT)
fused_step_kernel(const float* __restrict__ zin,   // torus state (or raw z0 if firstRaw)
                  const float* __restrict__ k1in,  // torus k1 (used iff skip1)
                  float* __restrict__ zout,        // torus next state (iff !lastOut)
                  float* __restrict__ outF,        // raw final output (iff lastOut)
                  const float* __restrict__ W1, const float* __restrict__ b1,
                  const float* __restrict__ W2, const float* __restrict__ b2,
                  int firstRaw, int skip1, int lastOut)
{
    extern __shared__ float s[];
    const int tid  = threadIdx.x;
    const int m    = blockIdx.y;
    const int base = blockIdx.x * LT;
    const float h  = 1.0f / (float)NSTEPS;

    // ---- weights ----
    for (int i = tid; i < Hdim * Ndim * Kdim; i += NT) s[F_W1 + i] = W1[i];
    for (int i = tid; i < Hdim; i += NT)               s[F_B1 + i] = b1[i];
    for (int i = tid; i < Ndim * Hdim * Kdim; i += NT) {
        int co = i / (Hdim * Kdim);
        int r  = i - co * (Hdim * Kdim);
        int ci = r / Kdim, k = r - ci * Kdim;
        s[F_W2 + co * W2S + ci * 8 + k] = W2[i];       // pads k=5..7 never read
    }
    for (int i = tid; i < Ndim; i += NT)               s[F_B2 + i] = b2[i];

    // ---- z tile (torus wrap; firstRaw reads raw z0 interior at Gg+t) ----
    {
        const int zpitch = firstRaw ? Ldim : Pdim;
        const int zoff   = firstRaw ? Gg : 0;
        for (int j = tid; j < Ndim * ZS; j += NT) {
            int ci = j / ZS;
            int jj = j - ci * ZS;
            int t  = base - 12 + jj;
            if (t < 0) t += Pdim; else if (t >= Pdim) t -= Pdim;
            s[F_Z + ci * ZS + jj] = zin[(m * Ndim + ci) * zpitch + zoff + t];
        }
    }
    // ---- k1 tile from gmem when skipping stage 1 ----
    if (skip1) {
        for (int j = tid; j < Ndim * ZS; j += NT) {
            int ci = j / ZS;
            int jj = j - ci * ZS;
            int t  = base - 12 + jj;
            if (t < 0) t += Pdim; else if (t >= Pdim) t -= Pdim;
            s[F_KB + ci * ZS + jj] = k1in[(m * Ndim + ci) * Pdim + t];
        }
    }
    __syncthreads();

    // per-thread conv1 weights (co_a fixed across stages)
    const int co_a = tid >> 2;
    const int psub = tid & 3;
    float w1r[Ndim][Kdim];
#pragma unroll
    for (int ci = 0; ci < Ndim; ci++)
#pragma unroll
        for (int k = 0; k < Kdim; k++)
            w1r[ci][k] = s[F_W1 + (co_a * Ndim + ci) * Kdim + k];
    const float b1c = s[F_B1 + co_a];
    const float b2c = s[F_B2 + (tid & 3)];

    const float AL[3] = {1.0f, 0.75f, 1.0f / 3.0f};
    const float BE[3] = {0.0f, 0.25f, 2.0f / 3.0f};
    const float GA[3] = {h, 0.25f * h, (2.0f / 3.0f) * h};

    for (int st = skip1 ? 1 : 0; st < 3; st++) {
        const float* uin = &s[(st == 0) ? F_Z : F_KB];

        // ---- Phase A: h1[hj] = tanh(conv1(uin)), hj in [0, AW) ----
        for (int hq = psub; hq < AW / 4; hq += 4) {
            const int jh0 = hq * 4;
            float acc[4] = {b1c, b1c, b1c, b1c};
#pragma unroll
            for (int ci = 0; ci < Ndim; ci++) {
                const float* up = uin + ci * ZS + jh0;
                float4 va = *(const float4*)(up);
                float4 vb = *(const float4*)(up + 4);
                float x[8] = {va.x, va.y, va.z, va.w, vb.x, vb.y, vb.z, vb.w};
#pragma unroll
                for (int j = 0; j < 4; j++)
#pragma unroll
                    for (int k = 0; k < Kdim; k++)
                        acc[j] = fmaf(w1r[ci][k], x[j + k], acc[j]);
            }
            float4 hv;
            hv.x = my_tanh(acc[0]);
            hv.y = my_tanh(acc[1]);
            hv.z = my_tanh(acc[2]);
            hv.w = my_tanh(acc[3]);
            *(float4*)&s[F_H + co_a * HS + jh0] = hv;
        }
        __syncthreads();

        // ---- Phase B: out[oj] = AL*z + BE*uin + GA*(conv2(h1)+b2) ----
        {
            const int co = tid & 3;
            const float al = AL[st], be = BE[st], ga = GA[st];
            const float* wb   = &s[F_W2 + co * W2S];
            const float* zrow = &s[F_Z + co * ZS];
            const float* urow = uin + co * ZS;
            float* krow = &s[F_KB + co * ZS];

            for (int q = tid >> 2; q < BW / 4; q += 64) {
                const int oj = q * 4;
                float a0 = 0.f, a1 = 0.f, a2 = 0.f, a3 = 0.f;
                const float* hb = &s[F_H + oj];
#pragma unroll 4
                for (int ci = 0; ci < Hdim; ci++) {
                    const float* hp = hb + ci * HS;
                    float4 va = *(const float4*)(hp);
                    float4 vb = *(const float4*)(hp + 4);
                    const float* wp = wb + ci * 8;
                    float4 w4 = *(const float4*)(wp);
                    float  wk = wp[4];

                    a0 = fmaf(w4.x, va.x, a0);
                    a1 = fmaf(w4.x, va.y, a1);
                    a2 = fmaf(w4.x, va.z, a2);
                    a3 = fmaf(w4.x, va.w, a3);
                    a0 = fmaf(w4.y, va.y, a0);
                    a1 = fmaf(w4.y, va.z, a1);
                    a2 = fmaf(w4.y, va.w, a2);
                    a3 = fmaf(w4.y, vb.x, a3);
                    a0 = fmaf(w4.z, va.z, a0);
                    a1 = fmaf(w4.z, va.w, a1);
                    a2 = fmaf(w4.z, vb.x, a2);
                    a3 = fmaf(w4.z, vb.y, a3);
                    a0 = fmaf(w4.w, va.w, a0);
                    a1 = fmaf(w4.w, vb.x, a1);
                    a2 = fmaf(w4.w, vb.y, a2);
                    a3 = fmaf(w4.w, vb.z, a3);
                    a0 = fmaf(wk, vb.x, a0);
                    a1 = fmaf(wk, vb.y, a1);
                    a2 = fmaf(wk, vb.z, a2);
                    a3 = fmaf(wk, vb.w, a3);
                }
                float4 zq = *(const float4*)(zrow + oj + 4);
                float4 uq = *(const float4*)(urow + oj + 4);
                float4 kv;
                kv.x = al * zq.x + be * uq.x + ga * (a0 + b2c);
                kv.y = al * zq.y + be * uq.y + ga * (a1 + b2c);
                kv.z = al * zq.z + be * uq.z + ga * (a2 + b2c);
                kv.w = al * zq.w + be * uq.w + ga * (a3 + b2c);
                *(float4*)(krow + oj + 4) = kv;      // in-place k update (safe)
            }
        }
        __syncthreads();
    }

    // ---- epilogue: KB slot (p+12) holds z_new at torus t = base + p ----
    const int Wt = (Pdim - base < LT) ? (Pdim - base) : LT;
    if (!lastOut) {
#pragma unroll
        for (int ci = 0; ci < Ndim; ci++) {
            float* zo = &zout[(m * Ndim + ci) * Pdim + base];
            const float* kb = &s[F_KB + ci * ZS + 12];
            for (int p = tid; p < Wt; p += NT) zo[p] = kb[p];
        }
    } else {
#pragma unroll
        for (int ci = 0; ci < Ndim; ci++) {
            const int row = (m * Ndim + ci) * Ldim;
            const float* kb = &s[F_KB + ci * ZS + 12];
            for (int p = tid; p < Wt; p += NT) {
                float v = kb[p];
                int t = base + p;
                outF[row + Gg + t] = v;                              // interior
                if (t < Gg)         outF[row + Ldim - Gg + t] = v;   // upper ghosts
                if (t >= Pdim - Gg) outF[row + t - (Pdim - Gg)] = v; // lower ghosts
            }
        }
    }
}

extern "C" void kernel_launch(void* const* d_in, const int* in_sizes, int n_in,
                              void* d_out, int out_size) {
    const float* z0 = (const float*)d_in[0];
    const float* W1 = (const float*)d_in[1];
    const float* b1 = (const float*)d_in[2];
    const float* W2 = (const float*)d_in[3];
    const float* b2 = (const float*)d_in[4];
    float* out = (float*)d_out;

    float *K1, *S0, *S1;
    cudaGetSymbolAddress((void**)&K1, g_k1);
    cudaGetSymbolAddress((void**)&S0, g_s0);
    cudaGetSymbolAddress((void**)&S1, g_s1);

    const size_t smem1 = S_TOT * sizeof(float);
    const size_t smemF = F_TOT * sizeof(float);
    cudaFuncSetAttribute(stage1_raw_kernel,
                         cudaFuncAttributeMaxDynamicSharedMemorySize, (int)smem1);
    cudaFuncSetAttribute(fused_step_kernel,
                         cudaFuncAttributeMaxDynamicSharedMemorySize, (int)smemF);

    dim3 grid1(NTILES1, Mdim);
    dim3 gridF(NTILES, Mdim);
    dim3 blk(NT);
    const float h = 1.0f / (float)NSTEPS;

    // Step 1, stage 1: raw domain (z0 ghosts are NOT periodic) -> torus k1
    stage1_raw_kernel<<<grid1, blk, smem1>>>(z0, K1, W1, b1, W2, b2, h);
    // Step 1, stages 2-3: fused, z read raw-interior, k1 from gmem
    fused_step_kernel<<<gridF, blk, smemF>>>(z0, K1, S0, out, W1, b1, W2, b2,
                                             /*firstRaw=*/1, /*skip1=*/1, /*last=*/0);
    // Steps 2..NSTEPS: fully fused on the torus
    float* cur = S0;
    float* nxt = S1;
    for (int st = 1; st < NSTEPS; st++) {
        int last = (st == NSTEPS - 1);
        fused_step_kernel<<<gridF, blk, smemF>>>(cur, K1, nxt, out, W1, b1, W2, b2,
                                                 0, 0, last);
        float* tmp = cur; cur = nxt; nxt = tmp;
    }
}